// round 8
// baseline (speedup 1.0000x reference)
#include <cuda_runtime.h>
#include <cuda_bf16.h>
#include <mma.h>
#include <math.h>
#include <cstdint>

using namespace nvcuda;
typedef __nv_bfloat16 bf16;

#define B_   8
#define NN   1024
#define D_   512
#define H_   8
#define DH_  64
#define GH_  32
#define BH_  (B_*H_)
#define TAB  128

// Scratch (device globals)
__device__ float g_Ab[(size_t)B_*NN*NN];
__device__ float g_tab[129*129];
__device__ bf16 g_qkvh[3u*BH_*NN*DH_];
__device__ bf16 g_qkvl[3u*BH_*NN*DH_];
__device__ bf16 g_xh[(size_t)B_*NN*D_];
__device__ bf16 g_xl[(size_t)B_*NN*D_];
__device__ bf16 g_Wqh[3*D_*D_];
__device__ bf16 g_Wql[3*D_*D_];
__device__ bf16 g_Wph[D_*D_];
__device__ bf16 g_Wpl[D_*D_];
__device__ bf16 g_Oh[(size_t)B_*NN*D_];
__device__ bf16 g_Ol[(size_t)B_*NN*D_];

// ---------------------------------------------------------------------------
__device__ __forceinline__ void cp16(void* smem_ptr, const void* gptr) {
    uint32_t s = (uint32_t)__cvta_generic_to_shared(smem_ptr);
    asm volatile("cp.async.cg.shared.global [%0], [%1], 16;" :: "r"(s), "l"(gptr));
}
#define CP_COMMIT() asm volatile("cp.async.commit_group;")
#define CP_WAIT(n)  asm volatile("cp.async.wait_group %0;" :: "n"(n))

__device__ __forceinline__ uint32_t pack_bf2(float a, float b) {
    __nv_bfloat162 t = __halves2bfloat162(__float2bfloat16(a), __float2bfloat16(b));
    return *reinterpret_cast<uint32_t*>(&t);
}

// ---------------------------------------------------------------------------
// K0: fp32 -> bf16 hi/lo split, three tensors in one launch
// ---------------------------------------------------------------------------
#define NX_ (B_*NN*D_)
#define NQ_ (3*D_*D_)
#define NP_ (D_*D_)
__global__ __launch_bounds__(256) void k0_conv3(
    const float* __restrict__ x, const float* __restrict__ wq,
    const float* __restrict__ wp)
{
    int idx = blockIdx.x * 256 + threadIdx.x;
    const float* src; bf16 *hi, *lo; int off;
    if (idx < NX_)             { src = x;  hi = g_xh;  lo = g_xl;  off = idx; }
    else if (idx < NX_ + NQ_)  { src = wq; hi = g_Wqh; lo = g_Wql; off = idx - NX_; }
    else if (idx < NX_+NQ_+NP_){ src = wp; hi = g_Wph; lo = g_Wpl; off = idx - NX_ - NQ_; }
    else return;
    float v = src[off];
    bf16 h = __float2bfloat16(v);
    hi[off] = h;
    lo[off] = __float2bfloat16(v - __bfloat162float(h));
}

// ---------------------------------------------------------------------------
// KTAB: build gate table g(a,p), exact erf GELU
// ---------------------------------------------------------------------------
__global__ __launch_bounds__(256) void ktab_build(
    const float* __restrict__ Wg1, const float* __restrict__ bg1,
    const float* __restrict__ Wg2, const float* __restrict__ bg2)
{
    int idx = blockIdx.x * 256 + threadIdx.x;
    if (idx >= 129*129) return;
    const float a = (float)(idx % 129) / (float)TAB;
    const float p = (float)(idx / 129) / (float)TAB;
    float z = bg2[0];
    #pragma unroll 4
    for (int j = 0; j < GH_; j++) {
        float hpre = fmaf(Wg1[j*2], a, fmaf(Wg1[j*2+1], p, bg1[j]));
        float ge   = 0.5f * hpre * (1.0f + erff(hpre * 0.70710678118654752f));
        z = fmaf(Wg2[j], ge, z);
    }
    g_tab[idx] = 1.0f / (1.0f + expf(-z));
}

// ---------------------------------------------------------------------------
// K2: gate via bilinear table lookup -> A_blended
// ---------------------------------------------------------------------------
__global__ __launch_bounds__(256) void k2_gate_tab(
    const float* __restrict__ Ae, const float* __restrict__ Ap)
{
    const size_t idx = (size_t)blockIdx.x * 256 + threadIdx.x;
    const float a = Ae[idx];
    const float p = Ap[idx];
    float af = fminf(fmaxf(a, 0.0f), 0.999995f) * (float)TAB;
    float pf = fminf(fmaxf(p, 0.0f), 0.999995f) * (float)TAB;
    int ia = (int)af, ip = (int)pf;
    float fa = af - ia, fp = pf - ip;
    const float* t0 = g_tab + ip*129 + ia;
    float g00 = t0[0],   g01 = t0[1];
    float g10 = t0[129], g11 = t0[130];
    float g0 = fmaf(fa, g01 - g00, g00);
    float g1 = fmaf(fa, g11 - g10, g10);
    float g  = fmaf(fp, g1 - g0, g0);
    g_Ab[idx] = fmaf(g, a - p, p);
}

// ---------------------------------------------------------------------------
// WMMA 128x128 GEMM tile with cp.async double buffering
// ---------------------------------------------------------------------------
#define ASLD 40
#define CSLD 136
#define STAGE_B 40960
#define SM_GEMM_BYTES (2*STAGE_B)

__device__ __forceinline__ void wmma_gemm_cp(
    const bf16* __restrict__ Ah, const bf16* __restrict__ Al,
    const bf16* __restrict__ Bh, const bf16* __restrict__ Bl,
    int lda, int ldb, int Ktot, int m0, int n0, char* sm)
{
    const int t   = threadIdx.x;
    const int wid = t >> 5;
    const int wm  = (wid >> 1) * 32;
    const int wn  = (wid & 1) * 64;

    wmma::fragment<wmma::accumulator, 16,16,16, float> acc[2][4];
    #pragma unroll
    for (int i = 0; i < 2; i++)
        #pragma unroll
        for (int j = 0; j < 4; j++) wmma::fill_fragment(acc[i][j], 0.0f);

    const int niter = Ktot / 32;
    auto issue = [&](int ch, int s) {
        const int kk = ch * 32;
        #pragma unroll
        for (int k = 0; k < 8; k++) {
            int c = k * 256 + t;
            int arr = c >> 9;
            int row = (c >> 2) & 127;
            int hh  = c & 3;
            const bf16* base = (arr == 0) ? Ah : (arr == 1) ? Al : (arr == 2) ? Bh : Bl;
            int roff = ((arr < 2) ? m0 : n0) + row;
            int ld   = (arr < 2) ? lda : ldb;
            cp16(sm + s*STAGE_B + arr*10240 + row*80 + hh*16,
                 base + (size_t)roff*ld + kk + hh*8);
        }
        CP_COMMIT();
    };

    issue(0, 0);
    for (int ch = 0; ch < niter; ch++) {
        const int s = ch & 1;
        if (ch + 1 < niter) { issue(ch + 1, s ^ 1); CP_WAIT(1); }
        else                { CP_WAIT(0); }
        __syncthreads();

        bf16* Ash = (bf16*)(sm + s*STAGE_B);
        bf16* Asl = Ash + 128*ASLD;
        bf16* Bsh = Asl + 128*ASLD;
        bf16* Bsl = Bsh + 128*ASLD;

        #pragma unroll
        for (int ks = 0; ks < 2; ks++) {
            const int ko = ks * 16;
            wmma::fragment<wmma::matrix_a, 16,16,16, bf16, wmma::row_major> ah[2], al[2];
            #pragma unroll
            for (int i = 0; i < 2; i++) {
                wmma::load_matrix_sync(ah[i], Ash + (wm + i*16)*ASLD + ko, ASLD);
                wmma::load_matrix_sync(al[i], Asl + (wm + i*16)*ASLD + ko, ASLD);
            }
            #pragma unroll
            for (int j = 0; j < 4; j++) {
                wmma::fragment<wmma::matrix_b, 16,16,16, bf16, wmma::col_major> bh, bl;
                wmma::load_matrix_sync(bh, Bsh + (wn + j*16)*ASLD + ko, ASLD);
                wmma::load_matrix_sync(bl, Bsl + (wn + j*16)*ASLD + ko, ASLD);
                #pragma unroll
                for (int i = 0; i < 2; i++) {
                    wmma::mma_sync(acc[i][j], ah[i], bh, acc[i][j]);
                    wmma::mma_sync(acc[i][j], ah[i], bl, acc[i][j]);
                    wmma::mma_sync(acc[i][j], al[i], bh, acc[i][j]);
                }
            }
        }
        __syncthreads();
    }

    float* Cs = (float*)sm;
    #pragma unroll
    for (int i = 0; i < 2; i++)
        #pragma unroll
        for (int j = 0; j < 4; j++)
            wmma::store_matrix_sync(Cs + (size_t)(wm + i*16)*CSLD + wn + j*16,
                                    acc[i][j], CSLD, wmma::mem_row_major);
    __syncthreads();
}

// ---------------------------------------------------------------------------
// K1: QKV = x @ W_qkv^T + b  -> scatter [3][B,H,N,DH] as bf16 hi/lo
// ---------------------------------------------------------------------------
__global__ __launch_bounds__(256, 2) void k1_qkv_mma(const float* __restrict__ bqkv)
{
    extern __shared__ char sm[];
    const int m0 = blockIdx.y * 128;
    const int n0 = blockIdx.x * 128;
    wmma_gemm_cp(g_xh, g_xl, g_Wqh, g_Wql, D_, D_, D_, m0, n0, sm);
    float* Cs = (float*)sm;

    const int t = threadIdx.x;
    for (int idx = t; idx < 128*128; idx += 256) {
        const int mi = idx >> 7, ni = idx & 127;
        const int m = m0 + mi, n = n0 + ni;
        const int b = m >> 10, iseq = m & 1023;
        const int cc = n >> 9, h = (n >> 6) & 7, d = n & 63;
        const float v = Cs[(size_t)mi*CSLD + ni] + bqkv[n];
        const size_t o = (((size_t)cc*B_ + b)*H_ + h)*NN*DH_ + (size_t)iseq*DH_ + d;
        bf16 hv = __float2bfloat16(v);
        g_qkvh[o] = hv;
        g_qkvl[o] = __float2bfloat16(v - __bfloat162float(hv));
    }
}

// ---------------------------------------------------------------------------
// K4: out = O @ W_proj^T + b_proj
// ---------------------------------------------------------------------------
__global__ __launch_bounds__(256, 2) void k4_proj_mma(
    const float* __restrict__ bp, float* __restrict__ out)
{
    extern __shared__ char sm[];
    const int m0 = blockIdx.y * 128;
    const int n0 = blockIdx.x * 128;
    wmma_gemm_cp(g_Oh, g_Ol, g_Wph, g_Wpl, D_, D_, D_, m0, n0, sm);
    float* Cs = (float*)sm;

    const int t = threadIdx.x;
    for (int idx = t; idx < 128*128; idx += 256) {
        const int mi = idx >> 7, ni = idx & 127;
        const int n = n0 + ni;
        out[(size_t)(m0 + mi) * D_ + n] = Cs[(size_t)mi*CSLD + ni] + bp[n];
    }
}

// ---------------------------------------------------------------------------
// KFLASH v2: 128 q-rows per CTA, 8 warps (16 rows each), separate S/P regions,
// K-next prefetch overlapped with PV-MMA. 1 CTA/SM (216 KB smem).
// ---------------------------------------------------------------------------
#define KF_QH 0                     // Q hi [128][80] bf16
#define KF_QL 20480                 // Q lo
#define KF_KH 40960                 // K hi [128][80] bf16 (overlaid by S)
#define KF_KL 61440                 // K lo
#define KF_S  40960                 // S f32 [128][136] (overlays K region)
#define KF_VH 110592                // V hi [128][80]
#define KF_VL 131072                // V lo
#define KF_PH 151552                // P hi [128][136] bf16
#define KF_PL 186368                // P lo
#define KF_RS 221184                // rowsum [128] f32
#define KF_BYTES 221696

__global__ __launch_bounds__(256) void kflash_mma(
    const float* __restrict__ Wb, const float* __restrict__ bb,
    const float* __restrict__ bsc)
{
    extern __shared__ char sm[];
    const int t    = threadIdx.x;
    const int wid  = t >> 5;
    const int lane = t & 31;
    const int mb   = blockIdx.x;         // 0..7
    const int bh   = blockIdx.y;         // 0..63
    const int b    = bh >> 3, h = bh & 7;
    const int m0   = mb * 128;

    const size_t Qoff = (size_t)bh * NN * DH_;
    const size_t Koff = ((size_t)BH_ + bh) * NN * DH_;
    const size_t Voff = ((size_t)2*BH_ + bh) * NN * DH_;
    const float* Abp  = g_Ab + (size_t)b * NN * NN;

    float* rowsum = (float*)(sm + KF_RS);
    if (t < 128) rowsum[t] = 0.0f;

    // Q tile (hi/lo): 2 arrays x 128 rows x 8 chunks = 2048 -> 8 rounds
    #pragma unroll
    for (int k = 0; k < 8; k++) {
        int c = k * 256 + t;
        int arr = c >> 10, row = (c >> 3) & 127, cc = c & 7;
        cp16(sm + (arr ? KF_QL : KF_QH) + row*160 + cc*16,
             (arr ? g_qkvl : g_qkvh) + Qoff + (size_t)(m0 + row)*DH_ + cc*8);
    }
    // K+V tile 0: 4 arrays x 128 x 8 = 4096 -> 16 rounds
    #pragma unroll
    for (int k = 0; k < 16; k++) {
        int c = k * 256 + t;
        int arr = c >> 10, row = (c >> 3) & 127, cc = c & 7;
        const bf16* gb = (arr == 0) ? g_qkvh + Koff : (arr == 1) ? g_qkvl + Koff
                       : (arr == 2) ? g_qkvh + Voff : g_qkvl + Voff;
        int dst = (arr == 0) ? KF_KH : (arr == 1) ? KF_KL
                : (arr == 2) ? KF_VH : KF_VL;
        cp16(sm + dst + row*160 + cc*16, gb + (size_t)row*DH_ + cc*8);
    }
    CP_COMMIT();

    const int wm = wid * 16;     // warp's 16 S/O rows

    wmma::fragment<wmma::accumulator, 16,16,16, float> accO[4];
    #pragma unroll
    for (int j = 0; j < 4; j++) wmma::fill_fragment(accO[j], 0.0f);

    const float wbh = Wb[h], bbh = bb[h], sch = bsc[h];

    for (int tile = 0; tile < 8; tile++) {
        CP_WAIT(0);
        __syncthreads();

        // --- S-MMA: warp computes rows [wm,wm+16) x all 128 cols, K=64 ---
        bf16* Qh = (bf16*)(sm + KF_QH);
        bf16* Ql = (bf16*)(sm + KF_QL);
        bf16* Kh = (bf16*)(sm + KF_KH);
        bf16* Kl = (bf16*)(sm + KF_KL);
        wmma::fragment<wmma::accumulator, 16,16,16, float> accS[8];
        #pragma unroll
        for (int j = 0; j < 8; j++) wmma::fill_fragment(accS[j], 0.0f);
        #pragma unroll
        for (int ks = 0; ks < 4; ks++) {
            const int ko = ks * 16;
            wmma::fragment<wmma::matrix_a, 16,16,16, bf16, wmma::row_major> ah, al;
            wmma::load_matrix_sync(ah, Qh + wm*80 + ko, 80);
            wmma::load_matrix_sync(al, Ql + wm*80 + ko, 80);
            #pragma unroll
            for (int j = 0; j < 8; j++) {
                wmma::fragment<wmma::matrix_b, 16,16,16, bf16, wmma::col_major> bh_f, bl_f;
                wmma::load_matrix_sync(bh_f, Kh + (j*16)*80 + ko, 80);
                wmma::load_matrix_sync(bl_f, Kl + (j*16)*80 + ko, 80);
                wmma::mma_sync(accS[j], ah, bh_f, accS[j]);
                wmma::mma_sync(accS[j], ah, bl_f, accS[j]);
                wmma::mma_sync(accS[j], al, bh_f, accS[j]);
            }
        }
        __syncthreads();        // all K reads done; S overlays K
        float* Ssm = (float*)(sm + KF_S);
        #pragma unroll
        for (int j = 0; j < 8; j++)
            wmma::store_matrix_sync(Ssm + wm*136 + j*16, accS[j], 136,
                                    wmma::mem_row_major);
        __syncthreads();

        // --- epilogue: warp-per-row streaming, 16 iters ---
        const int n0 = tile * 128;
        #pragma unroll 4
        for (int i = 0; i < 16; i++) {
            const int row = i*8 + wid;
            float4 s4 = *(const float4*)(Ssm + row*136 + lane*4);
            float4 a4 = *(const float4*)(Abp + (size_t)(m0 + row)*NN + n0 + lane*4);
            float sv[4] = {s4.x, s4.y, s4.z, s4.w};
            float av[4] = {a4.x, a4.y, a4.z, a4.w};
            float pq[4];
            float tot = 0.0f;
            #pragma unroll
            for (int q = 0; q < 4; q++) {
                float z  = fmaf(av[q], wbh, bbh);
                float sp = fmaxf(z, 0.0f) + __logf(1.0f + __expf(-fabsf(z)));
                float val = fmaf(sv[q], 0.125f, sp * sch);
                val = fminf(fmaxf(val, -50.0f), 50.0f);
                pq[q] = __expf(val);
                tot += pq[q];
            }
            uint2 hw, lw;
            hw.x = pack_bf2(pq[0], pq[1]); hw.y = pack_bf2(pq[2], pq[3]);
            bf16 h0 = __float2bfloat16(pq[0]), h1 = __float2bfloat16(pq[1]);
            bf16 h2 = __float2bfloat16(pq[2]), h3 = __float2bfloat16(pq[3]);
            lw.x = pack_bf2(pq[0]-__bfloat162float(h0), pq[1]-__bfloat162float(h1));
            lw.y = pack_bf2(pq[2]-__bfloat162float(h2), pq[3]-__bfloat162float(h3));
            *(uint2*)(sm + KF_PH + row*272 + lane*8) = hw;
            *(uint2*)(sm + KF_PL + row*272 + lane*8) = lw;
            #pragma unroll
            for (int off = 16; off > 0; off >>= 1)
                tot += __shfl_xor_sync(0xffffffffu, tot, off);
            if (lane == 0) rowsum[row] += tot;
        }
        __syncthreads();        // S dead, P ready

        // --- prefetch next K into (dead) K region, overlapping PV-MMA ---
        if (tile < 7) {
            const int nn = (tile + 1) * 128;
            #pragma unroll
            for (int k = 0; k < 8; k++) {
                int c = k * 256 + t;
                int arr = c >> 10, row = (c >> 3) & 127, cc = c & 7;
                cp16(sm + (arr ? KF_KL : KF_KH) + row*160 + cc*16,
                     (arr ? g_qkvl : g_qkvh) + Koff + (size_t)(nn + row)*DH_ + cc*8);
            }
            CP_COMMIT();
        }

        // --- PV-MMA: O[wm..wm+16) x 64, K=128 ---
        bf16* Ph = (bf16*)(sm + KF_PH);
        bf16* Pl = (bf16*)(sm + KF_PL);
        bf16* Vh = (bf16*)(sm + KF_VH);
        bf16* Vl = (bf16*)(sm + KF_VL);
        #pragma unroll
        for (int ks = 0; ks < 8; ks++) {
            const int ko = ks * 16;
            wmma::fragment<wmma::matrix_a, 16,16,16, bf16, wmma::row_major> pah, pal;
            wmma::load_matrix_sync(pah, Ph + wm*136 + ko, 136);
            wmma::load_matrix_sync(pal, Pl + wm*136 + ko, 136);
            #pragma unroll
            for (int j = 0; j < 4; j++) {
                wmma::fragment<wmma::matrix_b, 16,16,16, bf16, wmma::row_major> vbh, vbl;
                wmma::load_matrix_sync(vbh, Vh + ko*80 + j*16, 80);
                wmma::load_matrix_sync(vbl, Vl + ko*80 + j*16, 80);
                wmma::mma_sync(accO[j], pah, vbh, accO[j]);
                wmma::mma_sync(accO[j], pah, vbl, accO[j]);
                wmma::mma_sync(accO[j], pal, vbh, accO[j]);
            }
        }
        __syncthreads();        // V reads done

        // --- prefetch next V ---
        if (tile < 7) {
            const int nn = (tile + 1) * 128;
            #pragma unroll
            for (int k = 0; k < 8; k++) {
                int c = k * 256 + t;
                int arr = c >> 10, row = (c >> 3) & 127, cc = c & 7;
                cp16(sm + (arr ? KF_VL : KF_VH) + row*160 + cc*16,
                     (arr ? g_qkvl : g_qkvh) + Voff + (size_t)(nn + row)*DH_ + cc*8);
            }
            CP_COMMIT();
        }
    }

    // --- finalize: O / rowsum -> g_Oh/g_Ol ---
    float* Osm = (float*)(sm + KF_S);
    #pragma unroll
    for (int j = 0; j < 4; j++)
        wmma::store_matrix_sync(Osm + wm*72 + j*16, accO[j], 72,
                                wmma::mem_row_major);
    __syncthreads();
    {
        const int row = t >> 1;
        const int c0  = (t & 1) * 32;
        const float inv = 1.0f / rowsum[row];
        const size_t off = ((size_t)b*NN + m0 + row) * D_ + h*DH_ + c0;
        #pragma unroll
        for (int q = 0; q < 32; q++) {
            float o = Osm[row*72 + c0 + q] * inv;
            bf16 hv = __float2bfloat16(o);
            g_Oh[off + q] = hv;
            g_Ol[off + q] = __float2bfloat16(o - __bfloat162float(hv));
        }
    }
}

// ---------------------------------------------------------------------------
extern "C" void kernel_launch(void* const* d_in, const int* in_sizes, int n_in,
                              void* d_out, int out_size)
{
    const float* x    = (const float*)d_in[0];
    const float* Ae   = (const float*)d_in[1];
    const float* Ap   = (const float*)d_in[2];
    const float* Wqkv = (const float*)d_in[3];
    const float* bqkv = (const float*)d_in[4];
    const float* Wprj = (const float*)d_in[5];
    const float* bprj = (const float*)d_in[6];
    const float* Wg1  = (const float*)d_in[7];
    const float* bg1  = (const float*)d_in[8];
    const float* Wg2  = (const float*)d_in[9];
    const float* bg2  = (const float*)d_in[10];
    const float* Wb   = (const float*)d_in[11];
    const float* bb   = (const float*)d_in[12];
    const float* bsc  = (const float*)d_in[13];
    float* out = (float*)d_out;

    static bool init = false;
    if (!init) {
        cudaFuncSetAttribute(k1_qkv_mma,  cudaFuncAttributeMaxDynamicSharedMemorySize, SM_GEMM_BYTES);
        cudaFuncSetAttribute(k4_proj_mma, cudaFuncAttributeMaxDynamicSharedMemorySize, SM_GEMM_BYTES);
        cudaFuncSetAttribute(kflash_mma,  cudaFuncAttributeMaxDynamicSharedMemorySize, KF_BYTES);
        init = true;
    }

    const int ntot = NX_ + NQ_ + NP_;
    k0_conv3  <<<(ntot+255)/256, 256>>>(x, Wqkv, Wprj);
    ktab_build<<<(129*129+255)/256, 256>>>(Wg1, bg1, Wg2, bg2);
    k1_qkv_mma <<<dim3(12, 64), 256, SM_GEMM_BYTES>>>(bqkv);
    k2_gate_tab<<<(B_*NN*NN)/256, 256>>>(Ae, Ap);
    kflash_mma <<<dim3(8, 64), 256, KF_BYTES>>>(Wb, bb, bsc);
    k4_proj_mma<<<dim3(4, 64), 256, SM_GEMM_BYTES>>>(bprj, out);
}

// round 9
// speedup vs baseline: 1.1056x; 1.1056x over previous
#include <cuda_runtime.h>
#include <cuda_bf16.h>
#include <mma.h>
#include <math.h>
#include <cstdint>

using namespace nvcuda;
typedef __nv_bfloat16 bf16;

#define B_   8
#define NN   1024
#define D_   512
#define H_   8
#define DH_  64
#define GH_  32
#define BH_  (B_*H_)
#define TAB  128

// Scratch (device globals)
__device__ float g_Ab[(size_t)B_*NN*NN];
__device__ float g_tab[129*129];
__device__ float g_spt[H_*258];        // per-head softplus LUT (257 nodes + pad)
__device__ bf16 g_qkvh[3u*BH_*NN*DH_];
__device__ bf16 g_qkvl[3u*BH_*NN*DH_];
__device__ bf16 g_xh[(size_t)B_*NN*D_];
__device__ bf16 g_xl[(size_t)B_*NN*D_];
__device__ bf16 g_Wqh[3*D_*D_];
__device__ bf16 g_Wql[3*D_*D_];
__device__ bf16 g_Wph[D_*D_];
__device__ bf16 g_Wpl[D_*D_];
__device__ bf16 g_Oh[(size_t)B_*NN*D_];
__device__ bf16 g_Ol[(size_t)B_*NN*D_];

// ---------------------------------------------------------------------------
__device__ __forceinline__ void cp16(void* smem_ptr, const void* gptr) {
    uint32_t s = (uint32_t)__cvta_generic_to_shared(smem_ptr);
    asm volatile("cp.async.cg.shared.global [%0], [%1], 16;" :: "r"(s), "l"(gptr));
}
#define CP_COMMIT() asm volatile("cp.async.commit_group;")
#define CP_WAIT(n)  asm volatile("cp.async.wait_group %0;" :: "n"(n))

__device__ __forceinline__ uint32_t pack_bf2(float a, float b) {
    __nv_bfloat162 t = __halves2bfloat162(__float2bfloat16(a), __float2bfloat16(b));
    return *reinterpret_cast<uint32_t*>(&t);
}

// ---------------------------------------------------------------------------
// K0: fp32 -> bf16 hi/lo split, three tensors in one launch
// ---------------------------------------------------------------------------
#define NX_ (B_*NN*D_)
#define NQ_ (3*D_*D_)
#define NP_ (D_*D_)
__global__ __launch_bounds__(256) void k0_conv3(
    const float* __restrict__ x, const float* __restrict__ wq,
    const float* __restrict__ wp)
{
    int idx = blockIdx.x * 256 + threadIdx.x;
    const float* src; bf16 *hi, *lo; int off;
    if (idx < NX_)             { src = x;  hi = g_xh;  lo = g_xl;  off = idx; }
    else if (idx < NX_ + NQ_)  { src = wq; hi = g_Wqh; lo = g_Wql; off = idx - NX_; }
    else if (idx < NX_+NQ_+NP_){ src = wp; hi = g_Wph; lo = g_Wpl; off = idx - NX_ - NQ_; }
    else return;
    float v = src[off];
    bf16 h = __float2bfloat16(v);
    hi[off] = h;
    lo[off] = __float2bfloat16(v - __bfloat162float(h));
}

// ---------------------------------------------------------------------------
// KTAB: gate table g(a,p) (exact erf GELU) + per-head softplus LUT
// ---------------------------------------------------------------------------
__global__ __launch_bounds__(256) void ktab_build(
    const float* __restrict__ Wg1, const float* __restrict__ bg1,
    const float* __restrict__ Wg2, const float* __restrict__ bg2,
    const float* __restrict__ Wb,  const float* __restrict__ bb,
    const float* __restrict__ bsc)
{
    int idx = blockIdx.x * 256 + threadIdx.x;
    if (idx < 129*129) {
        const float a = (float)(idx % 129) / (float)TAB;
        const float p = (float)(idx / 129) / (float)TAB;
        float z = bg2[0];
        #pragma unroll 4
        for (int j = 0; j < GH_; j++) {
            float hpre = fmaf(Wg1[j*2], a, fmaf(Wg1[j*2+1], p, bg1[j]));
            float ge   = 0.5f * hpre * (1.0f + erff(hpre * 0.70710678118654752f));
            z = fmaf(Wg2[j], ge, z);
        }
        g_tab[idx] = 1.0f / (1.0f + expf(-z));
    } else if (idx < 129*129 + H_*257) {
        int r = idx - 129*129;
        int h = r / 257, i = r % 257;
        float ab = (float)i / 256.0f;
        float z  = fmaf(ab, Wb[h], bb[h]);
        float sp = fmaxf(z, 0.0f) + log1pf(expf(-fabsf(z)));
        g_spt[h*258 + i] = sp * bsc[h];
        if (i == 256) g_spt[h*258 + 257] = sp * bsc[h];   // pad
    }
}

// ---------------------------------------------------------------------------
// K2: gate via bilinear table lookup -> A_blended
// ---------------------------------------------------------------------------
__global__ __launch_bounds__(256) void k2_gate_tab(
    const float* __restrict__ Ae, const float* __restrict__ Ap)
{
    const size_t idx = (size_t)blockIdx.x * 256 + threadIdx.x;
    const float a = Ae[idx];
    const float p = Ap[idx];
    float af = fminf(fmaxf(a, 0.0f), 0.999995f) * (float)TAB;
    float pf = fminf(fmaxf(p, 0.0f), 0.999995f) * (float)TAB;
    int ia = (int)af, ip = (int)pf;
    float fa = af - ia, fp = pf - ip;
    const float* t0 = g_tab + ip*129 + ia;
    float g00 = t0[0],   g01 = t0[1];
    float g10 = t0[129], g11 = t0[130];
    float g0 = fmaf(fa, g01 - g00, g00);
    float g1 = fmaf(fa, g11 - g10, g10);
    float g  = fmaf(fp, g1 - g0, g0);
    g_Ab[idx] = fmaf(g, a - p, p);
}

// ---------------------------------------------------------------------------
// WMMA 128x128 GEMM tile with cp.async double buffering
// ---------------------------------------------------------------------------
#define ASLD 40
#define CSLD 136
#define STAGE_B 40960
#define SM_GEMM_BYTES (2*STAGE_B)

__device__ __forceinline__ void wmma_gemm_cp(
    const bf16* __restrict__ Ah, const bf16* __restrict__ Al,
    const bf16* __restrict__ Bh, const bf16* __restrict__ Bl,
    int lda, int ldb, int Ktot, int m0, int n0, char* sm)
{
    const int t   = threadIdx.x;
    const int wid = t >> 5;
    const int wm  = (wid >> 1) * 32;
    const int wn  = (wid & 1) * 64;

    wmma::fragment<wmma::accumulator, 16,16,16, float> acc[2][4];
    #pragma unroll
    for (int i = 0; i < 2; i++)
        #pragma unroll
        for (int j = 0; j < 4; j++) wmma::fill_fragment(acc[i][j], 0.0f);

    const int niter = Ktot / 32;
    auto issue = [&](int ch, int s) {
        const int kk = ch * 32;
        #pragma unroll
        for (int k = 0; k < 8; k++) {
            int c = k * 256 + t;
            int arr = c >> 9;
            int row = (c >> 2) & 127;
            int hh  = c & 3;
            const bf16* base = (arr == 0) ? Ah : (arr == 1) ? Al : (arr == 2) ? Bh : Bl;
            int roff = ((arr < 2) ? m0 : n0) + row;
            int ld   = (arr < 2) ? lda : ldb;
            cp16(sm + s*STAGE_B + arr*10240 + row*80 + hh*16,
                 base + (size_t)roff*ld + kk + hh*8);
        }
        CP_COMMIT();
    };

    issue(0, 0);
    for (int ch = 0; ch < niter; ch++) {
        const int s = ch & 1;
        if (ch + 1 < niter) { issue(ch + 1, s ^ 1); CP_WAIT(1); }
        else                { CP_WAIT(0); }
        __syncthreads();

        bf16* Ash = (bf16*)(sm + s*STAGE_B);
        bf16* Asl = Ash + 128*ASLD;
        bf16* Bsh = Asl + 128*ASLD;
        bf16* Bsl = Bsh + 128*ASLD;

        #pragma unroll
        for (int ks = 0; ks < 2; ks++) {
            const int ko = ks * 16;
            wmma::fragment<wmma::matrix_a, 16,16,16, bf16, wmma::row_major> ah[2], al[2];
            #pragma unroll
            for (int i = 0; i < 2; i++) {
                wmma::load_matrix_sync(ah[i], Ash + (wm + i*16)*ASLD + ko, ASLD);
                wmma::load_matrix_sync(al[i], Asl + (wm + i*16)*ASLD + ko, ASLD);
            }
            #pragma unroll
            for (int j = 0; j < 4; j++) {
                wmma::fragment<wmma::matrix_b, 16,16,16, bf16, wmma::col_major> bh, bl;
                wmma::load_matrix_sync(bh, Bsh + (wn + j*16)*ASLD + ko, ASLD);
                wmma::load_matrix_sync(bl, Bsl + (wn + j*16)*ASLD + ko, ASLD);
                #pragma unroll
                for (int i = 0; i < 2; i++) {
                    wmma::mma_sync(acc[i][j], ah[i], bh, acc[i][j]);
                    wmma::mma_sync(acc[i][j], ah[i], bl, acc[i][j]);
                    wmma::mma_sync(acc[i][j], al[i], bh, acc[i][j]);
                }
            }
        }
        __syncthreads();
    }

    float* Cs = (float*)sm;
    #pragma unroll
    for (int i = 0; i < 2; i++)
        #pragma unroll
        for (int j = 0; j < 4; j++)
            wmma::store_matrix_sync(Cs + (size_t)(wm + i*16)*CSLD + wn + j*16,
                                    acc[i][j], CSLD, wmma::mem_row_major);
    __syncthreads();
}

// ---------------------------------------------------------------------------
// K1: QKV = x @ W_qkv^T + b  -> scatter [3][B,H,N,DH] as bf16 hi/lo
// ---------------------------------------------------------------------------
__global__ __launch_bounds__(256, 2) void k1_qkv_mma(const float* __restrict__ bqkv)
{
    extern __shared__ char sm[];
    const int m0 = blockIdx.y * 128;
    const int n0 = blockIdx.x * 128;
    wmma_gemm_cp(g_xh, g_xl, g_Wqh, g_Wql, D_, D_, D_, m0, n0, sm);
    float* Cs = (float*)sm;

    const int t = threadIdx.x;
    for (int idx = t; idx < 128*128; idx += 256) {
        const int mi = idx >> 7, ni = idx & 127;
        const int m = m0 + mi, n = n0 + ni;
        const int b = m >> 10, iseq = m & 1023;
        const int cc = n >> 9, h = (n >> 6) & 7, d = n & 63;
        const float v = Cs[(size_t)mi*CSLD + ni] + bqkv[n];
        const size_t o = (((size_t)cc*B_ + b)*H_ + h)*NN*DH_ + (size_t)iseq*DH_ + d;
        bf16 hv = __float2bfloat16(v);
        g_qkvh[o] = hv;
        g_qkvl[o] = __float2bfloat16(v - __bfloat162float(hv));
    }
}

// ---------------------------------------------------------------------------
// K4: out = O @ W_proj^T + b_proj
// ---------------------------------------------------------------------------
__global__ __launch_bounds__(256, 2) void k4_proj_mma(
    const float* __restrict__ bp, float* __restrict__ out)
{
    extern __shared__ char sm[];
    const int m0 = blockIdx.y * 128;
    const int n0 = blockIdx.x * 128;
    wmma_gemm_cp(g_Oh, g_Ol, g_Wph, g_Wpl, D_, D_, D_, m0, n0, sm);
    float* Cs = (float*)sm;

    const int t = threadIdx.x;
    for (int idx = t; idx < 128*128; idx += 256) {
        const int mi = idx >> 7, ni = idx & 127;
        const int n = n0 + ni;
        out[(size_t)(m0 + mi) * D_ + n] = Cs[(size_t)mi*CSLD + ni] + bp[n];
    }
}

// ---------------------------------------------------------------------------
// KFLASH (R7 form, 64 q-rows, 2 CTAs/SM) + softplus LUT epilogue
// ---------------------------------------------------------------------------
#define KF_QH 0
#define KF_QL 10240
#define KF_VH 20480
#define KF_VL 40960
#define KF_U  61440
#define KF_RS 102400
#define KF_SPT 102656          // 258 floats
#define KF_BYTES 103688

__global__ __launch_bounds__(256, 2) void kflash_mma(const float* __restrict__ dummy)
{
    extern __shared__ char sm[];
    const int t   = threadIdx.x;
    const int wid = t >> 5;
    const int mb  = blockIdx.x;
    const int bh  = blockIdx.y;
    const int b   = bh >> 3, h = bh & 7;
    const int m0  = mb * 64;

    const size_t Qoff = (size_t)bh * NN * DH_;
    const size_t Koff = ((size_t)BH_ + bh) * NN * DH_;
    const size_t Voff = ((size_t)2*BH_ + bh) * NN * DH_;
    const float* Abp  = g_Ab + (size_t)b * NN * NN;

    float* spt = (float*)(sm + KF_SPT);
    for (int i = t; i < 258; i += 256) spt[i] = g_spt[h*258 + i];

    #pragma unroll
    for (int k = 0; k < 4; k++) {
        int c = k * 256 + t;
        int arr = c >> 9, row = (c >> 3) & 63, cc = c & 7;
        const bf16* src = (arr ? g_qkvl : g_qkvh) + Qoff + (size_t)(m0 + row)*DH_ + cc*8;
        cp16(sm + (arr ? KF_QL : KF_QH) + row*160 + cc*16, src);
    }
    CP_COMMIT();

    const int wmS = (wid >> 1) * 16, wnS = (wid & 1) * 64;
    const int wmO = (wid >> 1) * 16, wnO = (wid & 1) * 32;

    wmma::fragment<wmma::accumulator, 16,16,16, float> accO[2];
    #pragma unroll
    for (int j = 0; j < 2; j++) wmma::fill_fragment(accO[j], 0.0f);

    const int r_row = t >> 2;
    const int c0    = (t & 3) * 32;
    float rs = 0.0f;

    for (int tile = 0; tile < 8; tile++) {
        const int n0 = tile * 128;
        __syncthreads();

        #pragma unroll
        for (int k = 0; k < 16; k++) {
            int c = k * 256 + t;
            int arr = c >> 10, row = (c >> 3) & 127, cc = c & 7;
            const bf16* gb = (arr == 0) ? g_qkvh + Koff : (arr == 1) ? g_qkvl + Koff
                           : (arr == 2) ? g_qkvh + Voff : g_qkvl + Voff;
            char* db = (arr == 0) ? sm + KF_U : (arr == 1) ? sm + KF_U + 20480
                     : (arr == 2) ? sm + KF_VH : sm + KF_VL;
            cp16(db + row*160 + cc*16, gb + (size_t)(n0 + row)*DH_ + cc*8);
        }
        CP_COMMIT();
        CP_WAIT(0);
        __syncthreads();

        bf16* Qh = (bf16*)(sm + KF_QH);
        bf16* Ql = (bf16*)(sm + KF_QL);
        bf16* Kh = (bf16*)(sm + KF_U);
        bf16* Kl = (bf16*)(sm + KF_U + 20480);
        wmma::fragment<wmma::accumulator, 16,16,16, float> accS[4];
        #pragma unroll
        for (int j = 0; j < 4; j++) wmma::fill_fragment(accS[j], 0.0f);
        #pragma unroll
        for (int ks = 0; ks < 4; ks++) {
            const int ko = ks * 16;
            wmma::fragment<wmma::matrix_a, 16,16,16, bf16, wmma::row_major> ah, al;
            wmma::load_matrix_sync(ah, Qh + wmS*80 + ko, 80);
            wmma::load_matrix_sync(al, Ql + wmS*80 + ko, 80);
            #pragma unroll
            for (int j = 0; j < 4; j++) {
                wmma::fragment<wmma::matrix_b, 16,16,16, bf16, wmma::col_major> bh_f, bl_f;
                wmma::load_matrix_sync(bh_f, Kh + (wnS + j*16)*80 + ko, 80);
                wmma::load_matrix_sync(bl_f, Kl + (wnS + j*16)*80 + ko, 80);
                wmma::mma_sync(accS[j], ah, bh_f, accS[j]);
                wmma::mma_sync(accS[j], ah, bl_f, accS[j]);
                wmma::mma_sync(accS[j], al, bh_f, accS[j]);
            }
        }
        __syncthreads();
        float* Ssm = (float*)(sm + KF_U);
        #pragma unroll
        for (int j = 0; j < 4; j++)
            wmma::store_matrix_sync(Ssm + wmS*136 + wnS + j*16, accS[j], 136,
                                    wmma::mem_row_major);
        __syncthreads();

        // bias via per-head softplus LUT + clip + exp ; rowsum
        float pv[32];
        {
            const float* srow = Ssm + r_row*136 + c0;
            const float* abr  = Abp + (size_t)(m0 + r_row)*NN + n0 + c0;
            #pragma unroll
            for (int q = 0; q < 8; q++) {
                float4 s4 = ((const float4*)srow)[q];
                float4 a4 = ((const float4*)abr)[q];
                float sv[4] = {s4.x, s4.y, s4.z, s4.w};
                float av[4] = {a4.x, a4.y, a4.z, a4.w};
                #pragma unroll
                for (int kq = 0; kq < 4; kq++) {
                    float x = fminf(fmaxf(av[kq], 0.0f), 0.999996f) * 256.0f;
                    int ix = (int)x;
                    float fr = x - ix;
                    float sp = fmaf(fr, spt[ix+1] - spt[ix], spt[ix]);
                    float val = fmaf(sv[kq], 0.125f, sp);
                    val = fminf(fmaxf(val, -50.0f), 50.0f);
                    float pq = __expf(val);
                    rs += pq;
                    pv[q*4 + kq] = pq;
                }
            }
        }
        __syncthreads();
        {
            uint4* Php = (uint4*)((bf16*)(sm + KF_U) + r_row*136 + c0);
            uint4* Plp = (uint4*)((bf16*)(sm + KF_U + 17408) + r_row*136 + c0);
            #pragma unroll
            for (int w4 = 0; w4 < 4; w4++) {
                uint32_t hw[4], lw[4];
                #pragma unroll
                for (int q = 0; q < 4; q++) {
                    float v0 = pv[w4*8 + q*2], v1 = pv[w4*8 + q*2 + 1];
                    bf16 h0 = __float2bfloat16(v0), h1 = __float2bfloat16(v1);
                    hw[q] = pack_bf2(v0, v1);
                    lw[q] = pack_bf2(v0 - __bfloat162float(h0),
                                     v1 - __bfloat162float(h1));
                }
                Php[w4] = make_uint4(hw[0], hw[1], hw[2], hw[3]);
                Plp[w4] = make_uint4(lw[0], lw[1], lw[2], lw[3]);
            }
        }
        __syncthreads();

        bf16* Ph = (bf16*)(sm + KF_U);
        bf16* Pl = (bf16*)(sm + KF_U + 17408);
        bf16* Vh = (bf16*)(sm + KF_VH);
        bf16* Vl = (bf16*)(sm + KF_VL);
        #pragma unroll
        for (int ks = 0; ks < 8; ks++) {
            const int ko = ks * 16;
            wmma::fragment<wmma::matrix_a, 16,16,16, bf16, wmma::row_major> pah, pal;
            wmma::load_matrix_sync(pah, Ph + wmO*136 + ko, 136);
            wmma::load_matrix_sync(pal, Pl + wmO*136 + ko, 136);
            #pragma unroll
            for (int j = 0; j < 2; j++) {
                wmma::fragment<wmma::matrix_b, 16,16,16, bf16, wmma::row_major> vbh, vbl;
                wmma::load_matrix_sync(vbh, Vh + ko*80 + wnO + j*16, 80);
                wmma::load_matrix_sync(vbl, Vl + ko*80 + wnO + j*16, 80);
                wmma::mma_sync(accO[j], pah, vbh, accO[j]);
                wmma::mma_sync(accO[j], pah, vbl, accO[j]);
                wmma::mma_sync(accO[j], pal, vbh, accO[j]);
            }
        }
    }

    __syncthreads();
    float* Osm = (float*)(sm + KF_U);
    #pragma unroll
    for (int j = 0; j < 2; j++)
        wmma::store_matrix_sync(Osm + wmO*72 + wnO + j*16, accO[j], 72,
                                wmma::mem_row_major);
    rs += __shfl_xor_sync(0xffffffffu, rs, 1, 4);
    rs += __shfl_xor_sync(0xffffffffu, rs, 2, 4);
    float* rowsum = (float*)(sm + KF_RS);
    if ((t & 3) == 0) rowsum[r_row] = rs;
    __syncthreads();

    {
        const int r  = t >> 2;
        const int cc = (t & 3) * 16;
        const float inv = 1.0f / rowsum[r];
        const size_t off = ((size_t)b*NN + m0 + r) * D_ + h*DH_ + cc;
        #pragma unroll
        for (int q = 0; q < 16; q++) {
            float o = Osm[r*72 + cc + q] * inv;
            bf16 hv = __float2bfloat16(o);
            g_Oh[off + q] = hv;
            g_Ol[off + q] = __float2bfloat16(o - __bfloat162float(hv));
        }
    }
}

// ---------------------------------------------------------------------------
extern "C" void kernel_launch(void* const* d_in, const int* in_sizes, int n_in,
                              void* d_out, int out_size)
{
    const float* x    = (const float*)d_in[0];
    const float* Ae   = (const float*)d_in[1];
    const float* Ap   = (const float*)d_in[2];
    const float* Wqkv = (const float*)d_in[3];
    const float* bqkv = (const float*)d_in[4];
    const float* Wprj = (const float*)d_in[5];
    const float* bprj = (const float*)d_in[6];
    const float* Wg1  = (const float*)d_in[7];
    const float* bg1  = (const float*)d_in[8];
    const float* Wg2  = (const float*)d_in[9];
    const float* bg2  = (const float*)d_in[10];
    const float* Wb   = (const float*)d_in[11];
    const float* bb   = (const float*)d_in[12];
    const float* bsc  = (const float*)d_in[13];
    float* out = (float*)d_out;

    static bool init = false;
    if (!init) {
        cudaFuncSetAttribute(k1_qkv_mma,  cudaFuncAttributeMaxDynamicSharedMemorySize, SM_GEMM_BYTES);
        cudaFuncSetAttribute(k4_proj_mma, cudaFuncAttributeMaxDynamicSharedMemorySize, SM_GEMM_BYTES);
        cudaFuncSetAttribute(kflash_mma,  cudaFuncAttributeMaxDynamicSharedMemorySize, KF_BYTES);
        init = true;
    }

    const int ntot = NX_ + NQ_ + NP_;
    k0_conv3  <<<(ntot+255)/256, 256>>>(x, Wqkv, Wprj);
    ktab_build<<<(129*129 + H_*257 + 255)/256, 256>>>(Wg1, bg1, Wg2, bg2, Wb, bb, bsc);
    k1_qkv_mma <<<dim3(12, 64), 256, SM_GEMM_BYTES>>>(bqkv);
    k2_gate_tab<<<(B_*NN*NN)/256, 256>>>(Ae, Ap);
    kflash_mma <<<dim3(16, 64), 256, KF_BYTES>>>(nullptr);
    k4_proj_mma<<<dim3(4, 64), 256, SM_GEMM_BYTES>>>(bprj, out);
}

// round 10
// speedup vs baseline: 1.2009x; 1.0862x over previous
#include <cuda_runtime.h>
#include <cuda_bf16.h>
#include <mma.h>
#include <math.h>
#include <cstdint>

using namespace nvcuda;
typedef __nv_bfloat16 bf16;

#define B_   8
#define NN   1024
#define D_   512
#define H_   8
#define DH_  64
#define GH_  32
#define BH_  (B_*H_)
#define TAB  128

// Scratch (device globals)
__device__ float g_Ab[(size_t)B_*NN*NN];
__device__ float g_tab[129*129];
__device__ bf16 g_qkvh[3u*BH_*NN*DH_];
__device__ bf16 g_qkvl[3u*BH_*NN*DH_];
__device__ bf16 g_xh[(size_t)B_*NN*D_];
__device__ bf16 g_xl[(size_t)B_*NN*D_];
__device__ bf16 g_Wqh[3*D_*D_];
__device__ bf16 g_Wql[3*D_*D_];
__device__ bf16 g_Wph[D_*D_];
__device__ bf16 g_Wpl[D_*D_];
__device__ bf16 g_Oh[(size_t)B_*NN*D_];
__device__ bf16 g_Ol[(size_t)B_*NN*D_];

// ---------------------------------------------------------------------------
__device__ __forceinline__ void cp16(void* smem_ptr, const void* gptr) {
    uint32_t s = (uint32_t)__cvta_generic_to_shared(smem_ptr);
    asm volatile("cp.async.cg.shared.global [%0], [%1], 16;" :: "r"(s), "l"(gptr));
}
#define CP_COMMIT() asm volatile("cp.async.commit_group;")
#define CP_WAIT(n)  asm volatile("cp.async.wait_group %0;" :: "n"(n))

__device__ __forceinline__ uint32_t pack_bf2(float a, float b) {
    __nv_bfloat162 t = __halves2bfloat162(__float2bfloat16(a), __float2bfloat16(b));
    return *reinterpret_cast<uint32_t*>(&t);
}

// ---------------------------------------------------------------------------
// K0: fp32 -> bf16 hi/lo split, three tensors in one launch
// ---------------------------------------------------------------------------
#define NX_ (B_*NN*D_)
#define NQ_ (3*D_*D_)
#define NP_ (D_*D_)
__global__ __launch_bounds__(256) void k0_conv3(
    const float* __restrict__ x, const float* __restrict__ wq,
    const float* __restrict__ wp)
{
    int idx = blockIdx.x * 256 + threadIdx.x;
    const float* src; bf16 *hi, *lo; int off;
    if (idx < NX_)             { src = x;  hi = g_xh;  lo = g_xl;  off = idx; }
    else if (idx < NX_ + NQ_)  { src = wq; hi = g_Wqh; lo = g_Wql; off = idx - NX_; }
    else if (idx < NX_+NQ_+NP_){ src = wp; hi = g_Wph; lo = g_Wpl; off = idx - NX_ - NQ_; }
    else return;
    float v = src[off];
    bf16 h = __float2bfloat16(v);
    hi[off] = h;
    lo[off] = __float2bfloat16(v - __bfloat162float(h));
}

// ---------------------------------------------------------------------------
// KTAB: gate table g(a,p), exact erf GELU
// ---------------------------------------------------------------------------
__global__ __launch_bounds__(256) void ktab_build(
    const float* __restrict__ Wg1, const float* __restrict__ bg1,
    const float* __restrict__ Wg2, const float* __restrict__ bg2)
{
    int idx = blockIdx.x * 256 + threadIdx.x;
    if (idx >= 129*129) return;
    const float a = (float)(idx % 129) / (float)TAB;
    const float p = (float)(idx / 129) / (float)TAB;
    float z = bg2[0];
    #pragma unroll 4
    for (int j = 0; j < GH_; j++) {
        float hpre = fmaf(Wg1[j*2], a, fmaf(Wg1[j*2+1], p, bg1[j]));
        float ge   = 0.5f * hpre * (1.0f + erff(hpre * 0.70710678118654752f));
        z = fmaf(Wg2[j], ge, z);
    }
    g_tab[idx] = 1.0f / (1.0f + expf(-z));
}

// ---------------------------------------------------------------------------
// K2: gate via bilinear table lookup -> A_blended (4 elems/thread for ILP)
// ---------------------------------------------------------------------------
__global__ __launch_bounds__(256) void k2_gate_tab(
    const float* __restrict__ Ae, const float* __restrict__ Ap)
{
    const size_t base = ((size_t)blockIdx.x * 256 + threadIdx.x) * 4;
    float4 a4 = *(const float4*)(Ae + base);
    float4 p4 = *(const float4*)(Ap + base);
    float av[4] = {a4.x, a4.y, a4.z, a4.w};
    float pv[4] = {p4.x, p4.y, p4.z, p4.w};
    float rv[4];
    #pragma unroll
    for (int q = 0; q < 4; q++) {
        const float a = av[q], p = pv[q];
        float af = fminf(fmaxf(a, 0.0f), 0.999995f) * (float)TAB;
        float pf = fminf(fmaxf(p, 0.0f), 0.999995f) * (float)TAB;
        int ia = (int)af, ip = (int)pf;
        float fa = af - ia, fp = pf - ip;
        const float* t0 = g_tab + ip*129 + ia;
        float g00 = t0[0],   g01 = t0[1];
        float g10 = t0[129], g11 = t0[130];
        float g0 = fmaf(fa, g01 - g00, g00);
        float g1 = fmaf(fa, g11 - g10, g10);
        float g  = fmaf(fp, g1 - g0, g0);
        rv[q] = fmaf(g, a - p, p);
    }
    *(float4*)(g_Ab + base) = make_float4(rv[0], rv[1], rv[2], rv[3]);
}

// ---------------------------------------------------------------------------
// WMMA 128x128 GEMM tile with cp.async double buffering
// ---------------------------------------------------------------------------
#define ASLD 40
#define CSLD 136
#define STAGE_B 40960
#define SM_GEMM_BYTES (2*STAGE_B)

__device__ __forceinline__ void wmma_gemm_cp(
    const bf16* __restrict__ Ah, const bf16* __restrict__ Al,
    const bf16* __restrict__ Bh, const bf16* __restrict__ Bl,
    int lda, int ldb, int Ktot, int m0, int n0, char* sm)
{
    const int t   = threadIdx.x;
    const int wid = t >> 5;
    const int wm  = (wid >> 1) * 32;
    const int wn  = (wid & 1) * 64;

    wmma::fragment<wmma::accumulator, 16,16,16, float> acc[2][4];
    #pragma unroll
    for (int i = 0; i < 2; i++)
        #pragma unroll
        for (int j = 0; j < 4; j++) wmma::fill_fragment(acc[i][j], 0.0f);

    const int niter = Ktot / 32;
    auto issue = [&](int ch, int s) {
        const int kk = ch * 32;
        #pragma unroll
        for (int k = 0; k < 8; k++) {
            int c = k * 256 + t;
            int arr = c >> 9;
            int row = (c >> 2) & 127;
            int hh  = c & 3;
            const bf16* base = (arr == 0) ? Ah : (arr == 1) ? Al : (arr == 2) ? Bh : Bl;
            int roff = ((arr < 2) ? m0 : n0) + row;
            int ld   = (arr < 2) ? lda : ldb;
            cp16(sm + s*STAGE_B + arr*10240 + row*80 + hh*16,
                 base + (size_t)roff*ld + kk + hh*8);
        }
        CP_COMMIT();
    };

    issue(0, 0);
    for (int ch = 0; ch < niter; ch++) {
        const int s = ch & 1;
        if (ch + 1 < niter) { issue(ch + 1, s ^ 1); CP_WAIT(1); }
        else                { CP_WAIT(0); }
        __syncthreads();

        bf16* Ash = (bf16*)(sm + s*STAGE_B);
        bf16* Asl = Ash + 128*ASLD;
        bf16* Bsh = Asl + 128*ASLD;
        bf16* Bsl = Bsh + 128*ASLD;

        #pragma unroll
        for (int ks = 0; ks < 2; ks++) {
            const int ko = ks * 16;
            wmma::fragment<wmma::matrix_a, 16,16,16, bf16, wmma::row_major> ah[2], al[2];
            #pragma unroll
            for (int i = 0; i < 2; i++) {
                wmma::load_matrix_sync(ah[i], Ash + (wm + i*16)*ASLD + ko, ASLD);
                wmma::load_matrix_sync(al[i], Asl + (wm + i*16)*ASLD + ko, ASLD);
            }
            #pragma unroll
            for (int j = 0; j < 4; j++) {
                wmma::fragment<wmma::matrix_b, 16,16,16, bf16, wmma::col_major> bh, bl;
                wmma::load_matrix_sync(bh, Bsh + (wn + j*16)*ASLD + ko, ASLD);
                wmma::load_matrix_sync(bl, Bsl + (wn + j*16)*ASLD + ko, ASLD);
                #pragma unroll
                for (int i = 0; i < 2; i++) {
                    wmma::mma_sync(acc[i][j], ah[i], bh, acc[i][j]);
                    wmma::mma_sync(acc[i][j], ah[i], bl, acc[i][j]);
                    wmma::mma_sync(acc[i][j], al[i], bh, acc[i][j]);
                }
            }
        }
        __syncthreads();
    }

    float* Cs = (float*)sm;
    #pragma unroll
    for (int i = 0; i < 2; i++)
        #pragma unroll
        for (int j = 0; j < 4; j++)
            wmma::store_matrix_sync(Cs + (size_t)(wm + i*16)*CSLD + wn + j*16,
                                    acc[i][j], CSLD, wmma::mem_row_major);
    __syncthreads();
}

// ---------------------------------------------------------------------------
// K1: QKV = x @ W_qkv^T + b  -> scatter [3][B,H,N,DH] as bf16 hi/lo
// ---------------------------------------------------------------------------
__global__ __launch_bounds__(256, 2) void k1_qkv_mma(const float* __restrict__ bqkv)
{
    extern __shared__ char sm[];
    const int m0 = blockIdx.y * 128;
    const int n0 = blockIdx.x * 128;
    wmma_gemm_cp(g_xh, g_xl, g_Wqh, g_Wql, D_, D_, D_, m0, n0, sm);
    float* Cs = (float*)sm;

    const int t = threadIdx.x;
    for (int idx = t; idx < 128*128; idx += 256) {
        const int mi = idx >> 7, ni = idx & 127;
        const int m = m0 + mi, n = n0 + ni;
        const int b = m >> 10, iseq = m & 1023;
        const int cc = n >> 9, h = (n >> 6) & 7, d = n & 63;
        const float v = Cs[(size_t)mi*CSLD + ni] + bqkv[n];
        const size_t o = (((size_t)cc*B_ + b)*H_ + h)*NN*DH_ + (size_t)iseq*DH_ + d;
        bf16 hv = __float2bfloat16(v);
        g_qkvh[o] = hv;
        g_qkvl[o] = __float2bfloat16(v - __bfloat162float(hv));
    }
}

// ---------------------------------------------------------------------------
// K4: out = O @ W_proj^T + b_proj
// ---------------------------------------------------------------------------
__global__ __launch_bounds__(256, 2) void k4_proj_mma(
    const float* __restrict__ bp, float* __restrict__ out)
{
    extern __shared__ char sm[];
    const int m0 = blockIdx.y * 128;
    const int n0 = blockIdx.x * 128;
    wmma_gemm_cp(g_Oh, g_Ol, g_Wph, g_Wpl, D_, D_, D_, m0, n0, sm);
    float* Cs = (float*)sm;

    const int t = threadIdx.x;
    for (int idx = t; idx < 128*128; idx += 256) {
        const int mi = idx >> 7, ni = idx & 127;
        const int n = n0 + ni;
        out[(size_t)(m0 + mi) * D_ + n] = Cs[(size_t)mi*CSLD + ni] + bp[n];
    }
}

// ---------------------------------------------------------------------------
// KFLASH (R7 form, 64 q-rows, 2 CTAs/SM) — split K/V cp.async groups:
// wait K before S-MMA, wait V only before PV-MMA.
// ---------------------------------------------------------------------------
#define KF_QH 0
#define KF_QL 10240
#define KF_VH 20480
#define KF_VL 40960
#define KF_U  61440
#define KF_RS 102400
#define KF_BYTES 102656

__global__ __launch_bounds__(256, 2) void kflash_mma(
    const float* __restrict__ Wb, const float* __restrict__ bb,
    const float* __restrict__ bsc)
{
    extern __shared__ char sm[];
    const int t   = threadIdx.x;
    const int wid = t >> 5;
    const int mb  = blockIdx.x;
    const int bh  = blockIdx.y;
    const int b   = bh >> 3, h = bh & 7;
    const int m0  = mb * 64;

    const size_t Qoff = (size_t)bh * NN * DH_;
    const size_t Koff = ((size_t)BH_ + bh) * NN * DH_;
    const size_t Voff = ((size_t)2*BH_ + bh) * NN * DH_;
    const float* Abp  = g_Ab + (size_t)b * NN * NN;

    #pragma unroll
    for (int k = 0; k < 4; k++) {
        int c = k * 256 + t;
        int arr = c >> 9, row = (c >> 3) & 63, cc = c & 7;
        const bf16* src = (arr ? g_qkvl : g_qkvh) + Qoff + (size_t)(m0 + row)*DH_ + cc*8;
        cp16(sm + (arr ? KF_QL : KF_QH) + row*160 + cc*16, src);
    }
    CP_COMMIT();

    const int wmS = (wid >> 1) * 16, wnS = (wid & 1) * 64;
    const int wmO = (wid >> 1) * 16, wnO = (wid & 1) * 32;

    wmma::fragment<wmma::accumulator, 16,16,16, float> accO[2];
    #pragma unroll
    for (int j = 0; j < 2; j++) wmma::fill_fragment(accO[j], 0.0f);

    const int r_row = t >> 2;
    const int c0    = (t & 3) * 32;
    float rs = 0.0f;

    const float wbh = Wb[h], bbh = bb[h], sch = bsc[h];

    for (int tile = 0; tile < 8; tile++) {
        const int n0 = tile * 128;
        __syncthreads();     // prior-tile readers of U / V done

        // K group (arr 0..1): 8 rounds
        #pragma unroll
        for (int k = 0; k < 8; k++) {
            int c = k * 256 + t;
            int arr = c >> 10, row = (c >> 3) & 127, cc = c & 7;
            const bf16* gb = (arr == 0) ? g_qkvh + Koff : g_qkvl + Koff;
            char* db = (arr == 0) ? sm + KF_U : sm + KF_U + 20480;
            cp16(db + row*160 + cc*16, gb + (size_t)(n0 + row)*DH_ + cc*8);
        }
        CP_COMMIT();
        // V group (arr 0..1 -> Vh/Vl): 8 rounds
        #pragma unroll
        for (int k = 0; k < 8; k++) {
            int c = k * 256 + t;
            int arr = c >> 10, row = (c >> 3) & 127, cc = c & 7;
            const bf16* gb = (arr == 0) ? g_qkvh + Voff : g_qkvl + Voff;
            char* db = (arr == 0) ? sm + KF_VH : sm + KF_VL;
            cp16(db + row*160 + cc*16, gb + (size_t)(n0 + row)*DH_ + cc*8);
        }
        CP_COMMIT();

        CP_WAIT(1);          // K (and Q on tile 0) ready; V may be in flight
        __syncthreads();

        bf16* Qh = (bf16*)(sm + KF_QH);
        bf16* Ql = (bf16*)(sm + KF_QL);
        bf16* Kh = (bf16*)(sm + KF_U);
        bf16* Kl = (bf16*)(sm + KF_U + 20480);
        wmma::fragment<wmma::accumulator, 16,16,16, float> accS[4];
        #pragma unroll
        for (int j = 0; j < 4; j++) wmma::fill_fragment(accS[j], 0.0f);
        #pragma unroll
        for (int ks = 0; ks < 4; ks++) {
            const int ko = ks * 16;
            wmma::fragment<wmma::matrix_a, 16,16,16, bf16, wmma::row_major> ah, al;
            wmma::load_matrix_sync(ah, Qh + wmS*80 + ko, 80);
            wmma::load_matrix_sync(al, Ql + wmS*80 + ko, 80);
            #pragma unroll
            for (int j = 0; j < 4; j++) {
                wmma::fragment<wmma::matrix_b, 16,16,16, bf16, wmma::col_major> bh_f, bl_f;
                wmma::load_matrix_sync(bh_f, Kh + (wnS + j*16)*80 + ko, 80);
                wmma::load_matrix_sync(bl_f, Kl + (wnS + j*16)*80 + ko, 80);
                wmma::mma_sync(accS[j], ah, bh_f, accS[j]);
                wmma::mma_sync(accS[j], ah, bl_f, accS[j]);
                wmma::mma_sync(accS[j], al, bh_f, accS[j]);
            }
        }
        __syncthreads();     // all K reads done; U becomes S
        float* Ssm = (float*)(sm + KF_U);
        #pragma unroll
        for (int j = 0; j < 4; j++)
            wmma::store_matrix_sync(Ssm + wmS*136 + wnS + j*16, accS[j], 136,
                                    wmma::mem_row_major);
        __syncthreads();

        // bias + softplus + clip + exp ; rowsum
        float pv[32];
        {
            const float* srow = Ssm + r_row*136 + c0;
            const float* abr  = Abp + (size_t)(m0 + r_row)*NN + n0 + c0;
            #pragma unroll
            for (int q = 0; q < 8; q++) {
                float4 s4 = ((const float4*)srow)[q];
                float4 a4 = ((const float4*)abr)[q];
                float sv[4] = {s4.x, s4.y, s4.z, s4.w};
                float av[4] = {a4.x, a4.y, a4.z, a4.w};
                #pragma unroll
                for (int kq = 0; kq < 4; kq++) {
                    float z  = fmaf(av[kq], wbh, bbh);
                    float sp = fmaxf(z, 0.0f) + __logf(1.0f + __expf(-fabsf(z)));
                    float val = fmaf(sv[kq], 0.125f, sp * sch);
                    val = fminf(fmaxf(val, -50.0f), 50.0f);
                    float pq = __expf(val);
                    rs += pq;
                    pv[q*4 + kq] = pq;
                }
            }
        }
        __syncthreads();     // all S reads done; U becomes P
        {
            uint4* Php = (uint4*)((bf16*)(sm + KF_U) + r_row*136 + c0);
            uint4* Plp = (uint4*)((bf16*)(sm + KF_U + 17408) + r_row*136 + c0);
            #pragma unroll
            for (int w4 = 0; w4 < 4; w4++) {
                uint32_t hw[4], lw[4];
                #pragma unroll
                for (int q = 0; q < 4; q++) {
                    float v0 = pv[w4*8 + q*2], v1 = pv[w4*8 + q*2 + 1];
                    bf16 h0 = __float2bfloat16(v0), h1 = __float2bfloat16(v1);
                    hw[q] = pack_bf2(v0, v1);
                    lw[q] = pack_bf2(v0 - __bfloat162float(h0),
                                     v1 - __bfloat162float(h1));
                }
                Php[w4] = make_uint4(hw[0], hw[1], hw[2], hw[3]);
                Plp[w4] = make_uint4(lw[0], lw[1], lw[2], lw[3]);
            }
        }
        CP_WAIT(0);          // V ready (overlapped with S-MMA + epilogue)
        __syncthreads();

        bf16* Ph = (bf16*)(sm + KF_U);
        bf16* Pl = (bf16*)(sm + KF_U + 17408);
        bf16* Vh = (bf16*)(sm + KF_VH);
        bf16* Vl = (bf16*)(sm + KF_VL);
        #pragma unroll
        for (int ks = 0; ks < 8; ks++) {
            const int ko = ks * 16;
            wmma::fragment<wmma::matrix_a, 16,16,16, bf16, wmma::row_major> pah, pal;
            wmma::load_matrix_sync(pah, Ph + wmO*136 + ko, 136);
            wmma::load_matrix_sync(pal, Pl + wmO*136 + ko, 136);
            #pragma unroll
            for (int j = 0; j < 2; j++) {
                wmma::fragment<wmma::matrix_b, 16,16,16, bf16, wmma::row_major> vbh, vbl;
                wmma::load_matrix_sync(vbh, Vh + ko*80 + wnO + j*16, 80);
                wmma::load_matrix_sync(vbl, Vl + ko*80 + wnO + j*16, 80);
                wmma::mma_sync(accO[j], pah, vbh, accO[j]);
                wmma::mma_sync(accO[j], pah, vbl, accO[j]);
                wmma::mma_sync(accO[j], pal, vbh, accO[j]);
            }
        }
    }

    __syncthreads();
    float* Osm = (float*)(sm + KF_U);
    #pragma unroll
    for (int j = 0; j < 2; j++)
        wmma::store_matrix_sync(Osm + wmO*72 + wnO + j*16, accO[j], 72,
                                wmma::mem_row_major);
    rs += __shfl_xor_sync(0xffffffffu, rs, 1, 4);
    rs += __shfl_xor_sync(0xffffffffu, rs, 2, 4);
    float* rowsum = (float*)(sm + KF_RS);
    if ((t & 3) == 0) rowsum[r_row] = rs;
    __syncthreads();

    {
        const int r  = t >> 2;
        const int cc = (t & 3) * 16;
        const float inv = 1.0f / rowsum[r];
        const size_t off = ((size_t)b*NN + m0 + r) * D_ + h*DH_ + cc;
        #pragma unroll
        for (int q = 0; q < 16; q++) {
            float o = Osm[r*72 + cc + q] * inv;
            bf16 hv = __float2bfloat16(o);
            g_Oh[off + q] = hv;
            g_Ol[off + q] = __float2bfloat16(o - __bfloat162float(hv));
        }
    }
}

// ---------------------------------------------------------------------------
extern "C" void kernel_launch(void* const* d_in, const int* in_sizes, int n_in,
                              void* d_out, int out_size)
{
    const float* x    = (const float*)d_in[0];
    const float* Ae   = (const float*)d_in[1];
    const float* Ap   = (const float*)d_in[2];
    const float* Wqkv = (const float*)d_in[3];
    const float* bqkv = (const float*)d_in[4];
    const float* Wprj = (const float*)d_in[5];
    const float* bprj = (const float*)d_in[6];
    const float* Wg1  = (const float*)d_in[7];
    const float* bg1  = (const float*)d_in[8];
    const float* Wg2  = (const float*)d_in[9];
    const float* bg2  = (const float*)d_in[10];
    const float* Wb   = (const float*)d_in[11];
    const float* bb   = (const float*)d_in[12];
    const float* bsc  = (const float*)d_in[13];
    float* out = (float*)d_out;

    static bool init = false;
    if (!init) {
        cudaFuncSetAttribute(k1_qkv_mma,  cudaFuncAttributeMaxDynamicSharedMemorySize, SM_GEMM_BYTES);
        cudaFuncSetAttribute(k4_proj_mma, cudaFuncAttributeMaxDynamicSharedMemorySize, SM_GEMM_BYTES);
        cudaFuncSetAttribute(kflash_mma,  cudaFuncAttributeMaxDynamicSharedMemorySize, KF_BYTES);
        init = true;
    }

    const int ntot = NX_ + NQ_ + NP_;
    k0_conv3  <<<(ntot+255)/256, 256>>>(x, Wqkv, Wprj);
    ktab_build<<<(129*129+255)/256, 256>>>(Wg1, bg1, Wg2, bg2);
    k1_qkv_mma <<<dim3(12, 64), 256, SM_GEMM_BYTES>>>(bqkv);
    k2_gate_tab<<<(B_*NN*NN)/1024, 256>>>(Ae, Ap);
    kflash_mma <<<dim3(16, 64), 256, KF_BYTES>>>(Wb, bb, bsc);
    k4_proj_mma<<<dim3(4, 64), 256, SM_GEMM_BYTES>>>(bprj, out);
}